// round 11
// baseline (speedup 1.0000x reference)
#include <cuda_runtime.h>
#include <math.h>

// Problem constants
#define Bc 64
#define Nc 307
#define Tc 64
#define Fc 3
#define Hc 64
#define Rc (Bc * Nc)      // 19648 rows (b,n)
#define LN_EPS 1e-5f
#define ATS 320           // padded A-transpose stride (zero-filled padding)

// Scratch buffers (static device globals: allocation-free, graph-safe)
__device__ float g_buf0[Rc * Hc];   // z
__device__ float g_buf1[Rc * Hc];   // h1
__device__ float g_buf2[Rc * Hc];   // h2
__device__ float g_At[ATS * ATS];   // A transposed, padded; padding stays 0

__device__ __forceinline__ float* bufsel(int i) {
    return (i == 0) ? g_buf0 : ((i == 1) ? g_buf1 : g_buf2);
}

// ---------------------------------------------------------------------------
// k_transA: g_At[m][n] = A[n][m], zero-padded to 320x320.
// ---------------------------------------------------------------------------
__global__ void k_transA(const float* __restrict__ A)
{
    __shared__ float t[32][33];
    int bx = blockIdx.x * 32, by = blockIdx.y * 32;
    int tx = threadIdx.x, ty0 = threadIdx.y;   // 32 x 8

#pragma unroll
    for (int i = 0; i < 4; i++) {
        int ty = ty0 + 8 * i;
        int n = by + ty, m = bx + tx;
        t[ty][tx] = (n < Nc && m < Nc) ? A[(size_t)n * Nc + m] : 0.0f;
    }
    __syncthreads();
#pragma unroll
    for (int i = 0; i < 4; i++) {
        int ty = ty0 + 8 * i;
        g_At[(size_t)(bx + ty) * ATS + by + tx] = t[tx][ty];
    }
}

// ---------------------------------------------------------------------------
// k_init: z0 = x_seq[:,:,0,:] @ W_enc + b_enc ; pred_0 = z0 @ W_dec + b_dec
// ---------------------------------------------------------------------------
__global__ void __launch_bounds__(256) k_init(
    const float* __restrict__ x,
    const float* __restrict__ W_enc, const float* __restrict__ b_enc,
    const float* __restrict__ W_dec, const float* __restrict__ b_dec,
    float* __restrict__ out)
{
    int tid  = threadIdx.x;
    int warp = tid >> 5, lane = tid & 31;
    int r = blockIdx.x * 8 + warp;          // grid = Rc/8 exactly

    const float* xr = x + (size_t)r * Tc * Fc;   // t = 0
    float x0 = xr[0], x1 = xr[1], x2 = xr[2];

    float psum = 0.0f;
#pragma unroll
    for (int j = 0; j < 2; j++) {
        int c = lane + 32 * j;
        float z0 = x0 * W_enc[0 * Hc + c] + x1 * W_enc[1 * Hc + c]
                 + x2 * W_enc[2 * Hc + c] + b_enc[c];
        g_buf0[(size_t)r * Hc + c] = z0;
        psum += z0 * W_dec[c];
    }
#pragma unroll
    for (int o = 16; o; o >>= 1) psum += __shfl_xor_sync(0xffffffffu, psum, o);
    if (lane == 0) out[(size_t)r * Tc + 0] = psum + b_dec[0];
}

// ---------------------------------------------------------------------------
// k_gcn: fused GCN layer.
//   S[tile] = A[n0:n0+64, :] @ Z_b        (64x64 per block, K=307 in 32-chunks)
//   H[tile] = tanh(S @ W)                 (in-block epilogue, W smem-resident)
// 256 threads, 4x4 microtile. Grid: (5, 64) = 320 blocks.
// A tiles come from pre-transposed g_At (float4 loads, no guards).
// X tile is prefetched into registers across the sync (latency overlap).
// ---------------------------------------------------------------------------
__global__ void __launch_bounds__(256, 4) k_gcn(
    const float* __restrict__ W, int src, int dst)
{
    __shared__ __align__(16) float Ws[Hc * Hc];     // 16 KB
    __shared__ __align__(16) float Ast[32][68];     // [k][row]
    __shared__ __align__(16) float Xs[32][64];      // [k][col]
    __shared__ __align__(16) float Ss[64][68];      // S tile [row][k]

    const float* X = bufsel(src);
    float* C = bufsel(dst);

    int b  = blockIdx.y;
    int n0 = blockIdx.x * 64;
    int tid = threadIdx.x;
    int tx = tid & 15;        // col quad
    int ty = tid >> 4;        // row quad (0..15)

    // stage W (epilogue only; later syncs cover it)
    {
        const float4* w4 = (const float4*)W;
        float4* ws4 = (float4*)Ws;
#pragma unroll
        for (int i = 0; i < (Hc * Hc / 4) / 256; i++)
            ws4[tid + i * 256] = w4[tid + i * 256];
    }

    const float* Xb = X + (size_t)b * (Nc * Hc);
    float* Cb = C + (size_t)b * (Nc * Hc);

    float acc[4][4];
#pragma unroll
    for (int i = 0; i < 4; i++)
#pragma unroll
        for (int j = 0; j < 4; j++) acc[i][j] = 0.0f;

    // X prefetch: thread covers rows (tid>>4) and (tid>>4)+16, cols (tid&15)*4
    int xr_ = tid >> 4;
    int xc4 = (tid & 15) * 4;
    float4 px0, px1;
    {
        int k = xr_;
        px0 = (k < Nc) ? *(const float4*)(&Xb[(size_t)k * Hc + xc4])
                       : make_float4(0.f, 0.f, 0.f, 0.f);
        k = xr_ + 16;
        px1 = (k < Nc) ? *(const float4*)(&Xb[(size_t)k * Hc + xc4])
                       : make_float4(0.f, 0.f, 0.f, 0.f);
    }

    const int NCH = (Nc + 31) / 32;   // 10
#pragma unroll 1
    for (int c = 0; c < NCH; c++) {
        int k0 = c * 32;
        __syncthreads();               // previous chunk's compute done
        // store prefetched X tile
        *(float4*)(&Xs[xr_][xc4])      = px0;
        *(float4*)(&Xs[xr_ + 16][xc4]) = px1;
        // A tile: [32 k][64 row] from padded g_At (no guards needed)
        {
            int r4 = (tid & 15) * 4;
            int kk = tid >> 4;
            *(float4*)(&Ast[kk][r4]      ) = *(const float4*)(&g_At[(size_t)(k0 + kk)      * ATS + n0 + r4]);
            *(float4*)(&Ast[kk + 16][r4] ) = *(const float4*)(&g_At[(size_t)(k0 + kk + 16) * ATS + n0 + r4]);
        }
        // prefetch next X chunk (overlaps with compute below)
        if (c + 1 < NCH) {
            int kb = k0 + 32;
            int k = kb + xr_;
            px0 = (k < Nc) ? *(const float4*)(&Xb[(size_t)k * Hc + xc4])
                           : make_float4(0.f, 0.f, 0.f, 0.f);
            k = kb + xr_ + 16;
            px1 = (k < Nc) ? *(const float4*)(&Xb[(size_t)k * Hc + xc4])
                           : make_float4(0.f, 0.f, 0.f, 0.f);
        }
        __syncthreads();

#pragma unroll
        for (int kk = 0; kk < 32; kk++) {
            float4 a  = *(const float4*)(&Ast[kk][ty * 4]);
            float4 xv = *(const float4*)(&Xs[kk][tx * 4]);
            acc[0][0] += a.x * xv.x; acc[0][1] += a.x * xv.y;
            acc[0][2] += a.x * xv.z; acc[0][3] += a.x * xv.w;
            acc[1][0] += a.y * xv.x; acc[1][1] += a.y * xv.y;
            acc[1][2] += a.y * xv.z; acc[1][3] += a.y * xv.w;
            acc[2][0] += a.z * xv.x; acc[2][1] += a.z * xv.y;
            acc[2][2] += a.z * xv.z; acc[2][3] += a.z * xv.w;
            acc[3][0] += a.w * xv.x; acc[3][1] += a.w * xv.y;
            acc[3][2] += a.w * xv.z; acc[3][3] += a.w * xv.w;
        }
    }

    // Stash S tile to smem
#pragma unroll
    for (int i = 0; i < 4; i++) {
        float4 s = make_float4(acc[i][0], acc[i][1], acc[i][2], acc[i][3]);
        *(float4*)(&Ss[ty * 4 + i][tx * 4]) = s;
    }
    __syncthreads();

    // Epilogue: H = tanh(S @ W), k vectorized in steps of 4
    float o[4][4];
#pragma unroll
    for (int i = 0; i < 4; i++)
#pragma unroll
        for (int j = 0; j < 4; j++) o[i][j] = 0.0f;

#pragma unroll 2
    for (int k = 0; k < Hc; k += 4) {
        float4 w0 = *(const float4*)(&Ws[(k + 0) * Hc + tx * 4]);
        float4 w1 = *(const float4*)(&Ws[(k + 1) * Hc + tx * 4]);
        float4 w2 = *(const float4*)(&Ws[(k + 2) * Hc + tx * 4]);
        float4 w3 = *(const float4*)(&Ws[(k + 3) * Hc + tx * 4]);
#pragma unroll
        for (int i = 0; i < 4; i++) {
            float4 sv = *(const float4*)(&Ss[ty * 4 + i][k]);
            o[i][0] += sv.x * w0.x; o[i][1] += sv.x * w0.y;
            o[i][2] += sv.x * w0.z; o[i][3] += sv.x * w0.w;
            o[i][0] += sv.y * w1.x; o[i][1] += sv.y * w1.y;
            o[i][2] += sv.y * w1.z; o[i][3] += sv.y * w1.w;
            o[i][0] += sv.z * w2.x; o[i][1] += sv.z * w2.y;
            o[i][2] += sv.z * w2.z; o[i][3] += sv.z * w2.w;
            o[i][0] += sv.w * w3.x; o[i][1] += sv.w * w3.y;
            o[i][2] += sv.w * w3.z; o[i][3] += sv.w * w3.w;
        }
    }

#pragma unroll
    for (int i = 0; i < 4; i++) {
        int n = n0 + ty * 4 + i;
        if (n < Nc) {
            float4 h;
            h.x = tanhf(o[i][0]); h.y = tanhf(o[i][1]);
            h.z = tanhf(o[i][2]); h.w = tanhf(o[i][3]);
            *(float4*)(&Cb[(size_t)n * Hc + tx * 4]) = h;
        }
    }
}

// ---------------------------------------------------------------------------
// k_update: step tail, 32 rows per block, 256 threads.
// Phase 1 (warp per 4 rows): LN(h2) -> delta; zn = 2z + delta; zo = x@W_obs+b.
// Phase 2 (thread = 2 rows x 4 cols, k vectorized by 4):
//   gate = sigmoid([zn,zo]@W_gate + b); z' = zn + gate*(zo-zn)*mask;
//   pred_{t+1} = z'@W_dec + b_dec.
// ---------------------------------------------------------------------------
__global__ void __launch_bounds__(256) k_update(
    const float* __restrict__ x, int t,
    const float* __restrict__ mask,
    const float* __restrict__ ln_g, const float* __restrict__ ln_b,
    const float* __restrict__ W_obs, const float* __restrict__ b_obs,
    const float* __restrict__ W_gate, const float* __restrict__ b_gate,
    const float* __restrict__ W_dec, const float* __restrict__ b_dec,
    float* __restrict__ out)
{
    __shared__ __align__(16) float s_wg[2 * Hc * Hc];  // 32 KB, natural [k][c]
    __shared__ __align__(16) float s_zn[32][68];
    __shared__ __align__(16) float s_zo[32][68];
    __shared__ float s_m[32];

    int tid = threadIdx.x;
    // stage W_gate (float4)
    {
        const float4* w4 = (const float4*)W_gate;
        float4* sw4 = (float4*)s_wg;
#pragma unroll
        for (int i = 0; i < (2 * Hc * Hc / 4) / 256; i++)
            sw4[tid + i * 256] = w4[tid + i * 256];
    }

    int warp = tid >> 5, lane = tid & 31;
    int rbase = blockIdx.x * 32;             // grid = Rc/32 exactly (614)

    // Phase 1: each warp handles 4 rows
#pragma unroll
    for (int p = 0; p < 4; p++) {
        int lr = warp * 4 + p;               // local row 0..31
        int r = rbase + lr;

        float h0 = g_buf2[(size_t)r * Hc + lane];
        float h1 = g_buf2[(size_t)r * Hc + lane + 32];

        float s = h0 + h1;
#pragma unroll
        for (int o = 16; o; o >>= 1) s += __shfl_xor_sync(0xffffffffu, s, o);
        float mu = s * (1.0f / Hc);

        float d0 = h0 - mu, d1 = h1 - mu;
        float v = d0 * d0 + d1 * d1;
#pragma unroll
        for (int o = 16; o; o >>= 1) v += __shfl_xor_sync(0xffffffffu, v, o);
        float rstd = rsqrtf(v * (1.0f / Hc) + LN_EPS);

        const float* xr = x + ((size_t)r * Tc + (t + 1)) * Fc;
        float x0 = xr[0], x1 = xr[1], x2 = xr[2];

#pragma unroll
        for (int j = 0; j < 2; j++) {
            int c = lane + 32 * j;
            float hv = j ? h1 : h0;
            float delta = (hv - mu) * rstd * ln_g[c] + ln_b[c];
            float zn = 2.0f * g_buf0[(size_t)r * Hc + c] + delta;
            float zo = x0 * W_obs[0 * Hc + c] + x1 * W_obs[1 * Hc + c]
                     + x2 * W_obs[2 * Hc + c] + b_obs[c];
            s_zn[lr][c] = zn;
            s_zo[lr][c] = zo;
        }
        if (lane == 0) s_m[lr] = mask[r];
    }
    __syncthreads();

    // Phase 2: rg = tid>>4 (0..15) handles rows rg and rg+16; cols (tid&15)*4
    int rg = tid >> 4;
    int c4 = (tid & 15) * 4;

    float4 bg = *(const float4*)(&b_gate[c4]);
    float4 acc0 = bg, acc1 = bg;

#pragma unroll 4
    for (int k = 0; k < Hc; k += 4) {
        float4 z0v = *(const float4*)(&s_zn[rg][k]);
        float4 o0v = *(const float4*)(&s_zo[rg][k]);
        float4 z1v = *(const float4*)(&s_zn[rg + 16][k]);
        float4 o1v = *(const float4*)(&s_zo[rg + 16][k]);
#pragma unroll
        for (int j = 0; j < 4; j++) {
            float4 w0 = *(const float4*)(&s_wg[(k + j) * Hc + c4]);
            float4 w1 = *(const float4*)(&s_wg[(Hc + k + j) * Hc + c4]);
            float z0 = (j == 0) ? z0v.x : (j == 1) ? z0v.y : (j == 2) ? z0v.z : z0v.w;
            float o0 = (j == 0) ? o0v.x : (j == 1) ? o0v.y : (j == 2) ? o0v.z : o0v.w;
            float z1 = (j == 0) ? z1v.x : (j == 1) ? z1v.y : (j == 2) ? z1v.z : z1v.w;
            float o1 = (j == 0) ? o1v.x : (j == 1) ? o1v.y : (j == 2) ? o1v.z : o1v.w;
            acc0.x += z0 * w0.x + o0 * w1.x; acc0.y += z0 * w0.y + o0 * w1.y;
            acc0.z += z0 * w0.z + o0 * w1.z; acc0.w += z0 * w0.w + o0 * w1.w;
            acc1.x += z1 * w0.x + o1 * w1.x; acc1.y += z1 * w0.y + o1 * w1.y;
            acc1.z += z1 * w0.z + o1 * w1.z; acc1.w += z1 * w0.w + o1 * w1.w;
        }
    }

    float4 wd = *(const float4*)(&W_dec[c4]);

#pragma unroll
    for (int j = 0; j < 2; j++) {
        int lr = rg + 16 * j;
        int r = rbase + lr;
        float m = s_m[lr];
        float4 a = (j == 0) ? acc0 : acc1;
        float4 zn = *(const float4*)(&s_zn[lr][c4]);
        float4 zo = *(const float4*)(&s_zo[lr][c4]);
        float4 zf;
        zf.x = zn.x + (zo.x - zn.x) * m / (1.0f + expf(-a.x));
        zf.y = zn.y + (zo.y - zn.y) * m / (1.0f + expf(-a.y));
        zf.z = zn.z + (zo.z - zn.z) * m / (1.0f + expf(-a.z));
        zf.w = zn.w + (zo.w - zn.w) * m / (1.0f + expf(-a.w));

        *(float4*)(&g_buf0[(size_t)r * Hc + c4]) = zf;

        // pred: reduce zf . W_dec over 16 lanes of this row (half-warp group)
        float psum = zf.x * wd.x + zf.y * wd.y + zf.z * wd.z + zf.w * wd.w;
#pragma unroll
        for (int o = 8; o; o >>= 1) psum += __shfl_xor_sync(0xffffffffu, psum, o);
        if ((tid & 15) == 0) out[(size_t)r * Tc + (t + 1)] = psum + b_dec[0];
    }
}

// ---------------------------------------------------------------------------
// Host launcher (graph-capturable: kernel launches only)
// ---------------------------------------------------------------------------
extern "C" void kernel_launch(void* const* d_in, const int* in_sizes, int n_in,
                              void* d_out, int out_size)
{
    (void)in_sizes; (void)n_in; (void)out_size;
    const float* x_seq   = (const float*)d_in[0];
    const float* obs_mask= (const float*)d_in[1];
    const float* A       = (const float*)d_in[2];
    const float* W_enc   = (const float*)d_in[3];
    const float* b_enc   = (const float*)d_in[4];
    const float* W_gc1   = (const float*)d_in[5];
    const float* W_gc2   = (const float*)d_in[6];
    const float* ln_g    = (const float*)d_in[7];
    const float* ln_b    = (const float*)d_in[8];
    const float* W_obs   = (const float*)d_in[9];
    const float* b_obs   = (const float*)d_in[10];
    const float* W_gate  = (const float*)d_in[11];
    const float* b_gate  = (const float*)d_in[12];
    const float* W_dec   = (const float*)d_in[13];
    const float* b_dec   = (const float*)d_in[14];
    float* out = (float*)d_out;

    dim3 gcn_grid(5, Bc);   // ceil(307/64) x batches = 320 blocks

    // A transpose (padded, zero-filled) + z0 + pred_0
    dim3 tr_grid(10, 10), tr_blk(32, 8);
    k_transA<<<tr_grid, tr_blk>>>(A);
    k_init<<<Rc / 8, 256>>>(x_seq, W_enc, b_enc, W_dec, b_dec, out);

    for (int t = 0; t < Tc - 1; t++) {
        // h1 = tanh((A @ z) @ W_gc1)     (buf0 -> buf1)
        k_gcn<<<gcn_grid, 256>>>(W_gc1, 0, 1);
        // h2 = tanh((A @ h1) @ W_gc2)    (buf1 -> buf2)
        k_gcn<<<gcn_grid, 256>>>(W_gc2, 1, 2);
        // LN + z-update + gate + pred_{t+1}
        k_update<<<Rc / 32, 256>>>(x_seq, t, obs_mask, ln_g, ln_b,
                                   W_obs, b_obs, W_gate, b_gate,
                                   W_dec, b_dec, out);
    }
}

// round 12
// speedup vs baseline: 1.4826x; 1.4826x over previous
#include <cuda_runtime.h>
#include <math.h>

// Problem constants
#define Bc 64
#define Nc 307
#define Tc 64
#define Fc 3
#define Hc 64
#define Rc (Bc * Nc)      // 19648 rows (b,n)
#define LN_EPS 1e-5f

// Scratch buffers (static device globals: allocation-free, graph-safe)
__device__ float g_buf0[Rc * Hc];   // z
__device__ float g_buf1[Rc * Hc];   // h1
__device__ float g_buf2[Rc * Hc];   // h2

__device__ __forceinline__ float* bufsel(int i) {
    return (i == 0) ? g_buf0 : ((i == 1) ? g_buf1 : g_buf2);
}

// ---------------------------------------------------------------------------
// k_init: z0 = x_seq[:,:,0,:] @ W_enc + b_enc ; pred_0 = z0 @ W_dec + b_dec
// ---------------------------------------------------------------------------
__global__ void __launch_bounds__(256) k_init(
    const float* __restrict__ x,
    const float* __restrict__ W_enc, const float* __restrict__ b_enc,
    const float* __restrict__ W_dec, const float* __restrict__ b_dec,
    float* __restrict__ out)
{
    int tid  = threadIdx.x;
    int warp = tid >> 5, lane = tid & 31;
    int r = blockIdx.x * 8 + warp;          // grid = Rc/8 exactly

    const float* xr = x + (size_t)r * Tc * Fc;   // t = 0
    float x0 = xr[0], x1 = xr[1], x2 = xr[2];

    float psum = 0.0f;
#pragma unroll
    for (int j = 0; j < 2; j++) {
        int c = lane + 32 * j;
        float z0 = x0 * W_enc[0 * Hc + c] + x1 * W_enc[1 * Hc + c]
                 + x2 * W_enc[2 * Hc + c] + b_enc[c];
        g_buf0[(size_t)r * Hc + c] = z0;
        psum += z0 * W_dec[c];
    }
#pragma unroll
    for (int o = 16; o; o >>= 1) psum += __shfl_xor_sync(0xffffffffu, psum, o);
    if (lane == 0) out[(size_t)r * Tc + 0] = psum + b_dec[0];
}

// ---------------------------------------------------------------------------
// k_gcn: fused GCN layer (R9 structure; smem union for Ss to raise occupancy).
//   S[tile] = A[n0:n0+64, :] @ Z_b        (64x64 per block, K=307 in 32-chunks)
//   H[tile] = tanh(S @ W)                 (in-block epilogue, W smem-resident)
// 256 threads, 4x4 microtile. Grid: (5, 64) = 320 blocks.
// Ss (17.4 KB) aliases the Ast+Xs region (16.9 KB): total smem ~34 KB
// -> 4 blocks/SM (reg-limited), single wave for the 320-block grid.
// ---------------------------------------------------------------------------
__global__ void __launch_bounds__(256) k_gcn(
    const float* __restrict__ Amat, const float* __restrict__ W,
    int src, int dst)
{
    __shared__ __align__(16) float Ws[Hc * Hc];         // 16 KB
    __shared__ __align__(16) char u_raw[64 * 68 * 4];   // 17408 B union region
    float (*Ast)[68] = (float(*)[68])u_raw;             // 32*68*4 = 8704 B
    float (*Xs)[64]  = (float(*)[64])(u_raw + 8704);    // 32*64*4 = 8192 B
    float (*Ss)[68]  = (float(*)[68])u_raw;             // 64*68*4 = 17408 B (aliases)

    const float* X = bufsel(src);
    float* C = bufsel(dst);

    int b  = blockIdx.y;
    int n0 = blockIdx.x * 64;
    int tid = threadIdx.x;
    int tx = tid & 15;        // col quad
    int ty = tid >> 4;        // row quad (0..15)

    // stage W (used only in epilogue; mainloop syncs cover the hazard)
#pragma unroll
    for (int i = 0; i < (Hc * Hc) / 256; i++)
        Ws[tid + i * 256] = W[tid + i * 256];

    const float* Xb = X + (size_t)b * (Nc * Hc);
    float* Cb = C + (size_t)b * (Nc * Hc);

    float acc[4][4];
#pragma unroll
    for (int i = 0; i < 4; i++)
#pragma unroll
        for (int j = 0; j < 4; j++) acc[i][j] = 0.0f;

    for (int k0 = 0; k0 < Nc; k0 += 32) {
        __syncthreads();
        // Load A tile (64 rows x 32 k), transposed into Ast[k][row]
        {
            int kk = tid & 31, rr = tid >> 5;    // rr 0..7
            int k = k0 + kk;
#pragma unroll
            for (int i = 0; i < 8; i++) {
                int row = rr + i * 8;
                int n = n0 + row;
                Ast[kk][row] = (n < Nc && k < Nc) ? Amat[(size_t)n * Nc + k] : 0.0f;
            }
        }
        // Load X tile (32 k-rows x 64 cols), float4 coalesced
        {
            int rr = tid >> 4;           // 0..15
            int c4 = (tid & 15) * 4;
#pragma unroll
            for (int i = 0; i < 2; i++) {
                int row = rr + i * 16;
                int k = k0 + row;
                float4 vv;
                if (k < Nc) vv = *(const float4*)(&Xb[(size_t)k * Hc + c4]);
                else        vv = make_float4(0.f, 0.f, 0.f, 0.f);
                *(float4*)(&Xs[row][c4]) = vv;
            }
        }
        __syncthreads();

#pragma unroll
        for (int kk = 0; kk < 32; kk++) {
            float4 a  = *(const float4*)(&Ast[kk][ty * 4]);
            float4 xv = *(const float4*)(&Xs[kk][tx * 4]);
            acc[0][0] += a.x * xv.x; acc[0][1] += a.x * xv.y;
            acc[0][2] += a.x * xv.z; acc[0][3] += a.x * xv.w;
            acc[1][0] += a.y * xv.x; acc[1][1] += a.y * xv.y;
            acc[1][2] += a.y * xv.z; acc[1][3] += a.y * xv.w;
            acc[2][0] += a.z * xv.x; acc[2][1] += a.z * xv.y;
            acc[2][2] += a.z * xv.z; acc[2][3] += a.z * xv.w;
            acc[3][0] += a.w * xv.x; acc[3][1] += a.w * xv.y;
            acc[3][2] += a.w * xv.z; acc[3][3] += a.w * xv.w;
        }
    }

    // Aliasing hazard: wait for ALL warps to finish reading Ast/Xs
    __syncthreads();

    // Stash S tile to smem (overwrites Ast/Xs region)
#pragma unroll
    for (int i = 0; i < 4; i++) {
        float4 s = make_float4(acc[i][0], acc[i][1], acc[i][2], acc[i][3]);
        *(float4*)(&Ss[ty * 4 + i][tx * 4]) = s;
    }
    __syncthreads();

    // Epilogue: H = tanh(S @ W), same 4x4 microtile
    float o[4][4];
#pragma unroll
    for (int i = 0; i < 4; i++)
#pragma unroll
        for (int j = 0; j < 4; j++) o[i][j] = 0.0f;

#pragma unroll 4
    for (int k = 0; k < Hc; k++) {
        float4 w = *(const float4*)(&Ws[k * Hc + tx * 4]);
        float s0 = Ss[ty * 4 + 0][k];
        float s1 = Ss[ty * 4 + 1][k];
        float s2 = Ss[ty * 4 + 2][k];
        float s3 = Ss[ty * 4 + 3][k];
        o[0][0] += s0 * w.x; o[0][1] += s0 * w.y; o[0][2] += s0 * w.z; o[0][3] += s0 * w.w;
        o[1][0] += s1 * w.x; o[1][1] += s1 * w.y; o[1][2] += s1 * w.z; o[1][3] += s1 * w.w;
        o[2][0] += s2 * w.x; o[2][1] += s2 * w.y; o[2][2] += s2 * w.z; o[2][3] += s2 * w.w;
        o[3][0] += s3 * w.x; o[3][1] += s3 * w.y; o[3][2] += s3 * w.z; o[3][3] += s3 * w.w;
    }

#pragma unroll
    for (int i = 0; i < 4; i++) {
        int n = n0 + ty * 4 + i;
        if (n < Nc) {
            float4 h;
            h.x = tanhf(o[i][0]); h.y = tanhf(o[i][1]);
            h.z = tanhf(o[i][2]); h.w = tanhf(o[i][3]);
            *(float4*)(&Cb[(size_t)n * Hc + tx * 4]) = h;
        }
    }
}

// ---------------------------------------------------------------------------
// k_update: step tail, 32 rows per block, 256 threads (R9 version, measured).
// Phase 1 (warp per 4 rows): LN(h2) -> delta; zn = 2z + delta; zo = x@W_obs+b.
// Phase 2 (thread = 2 rows x 4 cols): gate = sigmoid([zn,zo]@W_gate + b);
//   z' = zn + gate*(zo-zn)*mask; pred_{t+1} = z'@W_dec + b_dec.
// ---------------------------------------------------------------------------
__global__ void __launch_bounds__(256) k_update(
    const float* __restrict__ x, int t,
    const float* __restrict__ mask,
    const float* __restrict__ ln_g, const float* __restrict__ ln_b,
    const float* __restrict__ W_obs, const float* __restrict__ b_obs,
    const float* __restrict__ W_gate, const float* __restrict__ b_gate,
    const float* __restrict__ W_dec, const float* __restrict__ b_dec,
    float* __restrict__ out)
{
    __shared__ __align__(16) float s_wg[2 * Hc * Hc];  // 32 KB, natural [k][c]
    __shared__ __align__(16) float s_zn[32][68];
    __shared__ __align__(16) float s_zo[32][68];
    __shared__ float s_m[32];

    int tid = threadIdx.x;
    // stage W_gate (float4)
    {
        const float4* w4 = (const float4*)W_gate;
        float4* sw4 = (float4*)s_wg;
#pragma unroll
        for (int i = 0; i < (2 * Hc * Hc / 4) / 256; i++)
            sw4[tid + i * 256] = w4[tid + i * 256];
    }

    int warp = tid >> 5, lane = tid & 31;
    int rbase = blockIdx.x * 32;             // grid = Rc/32 exactly (614)

    // Phase 1: each warp handles 4 rows
#pragma unroll
    for (int p = 0; p < 4; p++) {
        int lr = warp * 4 + p;               // local row 0..31
        int r = rbase + lr;

        float h0 = g_buf2[(size_t)r * Hc + lane];
        float h1 = g_buf2[(size_t)r * Hc + lane + 32];

        float s = h0 + h1;
#pragma unroll
        for (int o = 16; o; o >>= 1) s += __shfl_xor_sync(0xffffffffu, s, o);
        float mu = s * (1.0f / Hc);

        float d0 = h0 - mu, d1 = h1 - mu;
        float v = d0 * d0 + d1 * d1;
#pragma unroll
        for (int o = 16; o; o >>= 1) v += __shfl_xor_sync(0xffffffffu, v, o);
        float rstd = rsqrtf(v * (1.0f / Hc) + LN_EPS);

        const float* xr = x + ((size_t)r * Tc + (t + 1)) * Fc;
        float x0 = xr[0], x1 = xr[1], x2 = xr[2];

#pragma unroll
        for (int j = 0; j < 2; j++) {
            int c = lane + 32 * j;
            float hv = j ? h1 : h0;
            float delta = (hv - mu) * rstd * ln_g[c] + ln_b[c];
            float zn = 2.0f * g_buf0[(size_t)r * Hc + c] + delta;
            float zo = x0 * W_obs[0 * Hc + c] + x1 * W_obs[1 * Hc + c]
                     + x2 * W_obs[2 * Hc + c] + b_obs[c];
            s_zn[lr][c] = zn;
            s_zo[lr][c] = zo;
        }
        if (lane == 0) s_m[lr] = mask[r];
    }
    __syncthreads();

    // Phase 2: rg = tid>>4 (0..15) handles rows rg and rg+16; cols (tid&15)*4
    int rg = tid >> 4;
    int c4 = (tid & 15) * 4;

    float4 bg = *(const float4*)(&b_gate[c4]);
    float4 acc0 = bg, acc1 = bg;

#pragma unroll 4
    for (int k = 0; k < Hc; k++) {
        float4 w0 = *(const float4*)(&s_wg[k * Hc + c4]);
        float4 w1 = *(const float4*)(&s_wg[(Hc + k) * Hc + c4]);

        float z0 = s_zn[rg][k],      o0 = s_zo[rg][k];
        float z1 = s_zn[rg + 16][k], o1 = s_zo[rg + 16][k];

        acc0.x += z0 * w0.x + o0 * w1.x; acc0.y += z0 * w0.y + o0 * w1.y;
        acc0.z += z0 * w0.z + o0 * w1.z; acc0.w += z0 * w0.w + o0 * w1.w;
        acc1.x += z1 * w0.x + o1 * w1.x; acc1.y += z1 * w0.y + o1 * w1.y;
        acc1.z += z1 * w0.z + o1 * w1.z; acc1.w += z1 * w0.w + o1 * w1.w;
    }

    float4 wd = *(const float4*)(&W_dec[c4]);

#pragma unroll
    for (int j = 0; j < 2; j++) {
        int lr = rg + 16 * j;
        int r = rbase + lr;
        float m = s_m[lr];
        float4 a = (j == 0) ? acc0 : acc1;
        float4 zn = *(const float4*)(&s_zn[lr][c4]);
        float4 zo = *(const float4*)(&s_zo[lr][c4]);
        float4 zf;
        zf.x = zn.x + (zo.x - zn.x) * m / (1.0f + expf(-a.x));
        zf.y = zn.y + (zo.y - zn.y) * m / (1.0f + expf(-a.y));
        zf.z = zn.z + (zo.z - zn.z) * m / (1.0f + expf(-a.z));
        zf.w = zn.w + (zo.w - zn.w) * m / (1.0f + expf(-a.w));

        *(float4*)(&g_buf0[(size_t)r * Hc + c4]) = zf;

        // pred: reduce zf . W_dec over 16 lanes of this row (half-warp group)
        float psum = zf.x * wd.x + zf.y * wd.y + zf.z * wd.z + zf.w * wd.w;
#pragma unroll
        for (int o = 8; o; o >>= 1) psum += __shfl_xor_sync(0xffffffffu, psum, o);
        if ((tid & 15) == 0) out[(size_t)r * Tc + (t + 1)] = psum + b_dec[0];
    }
}

// ---------------------------------------------------------------------------
// Host launcher (graph-capturable: kernel launches only)
// ---------------------------------------------------------------------------
extern "C" void kernel_launch(void* const* d_in, const int* in_sizes, int n_in,
                              void* d_out, int out_size)
{
    (void)in_sizes; (void)n_in; (void)out_size;
    const float* x_seq   = (const float*)d_in[0];
    const float* obs_mask= (const float*)d_in[1];
    const float* A       = (const float*)d_in[2];
    const float* W_enc   = (const float*)d_in[3];
    const float* b_enc   = (const float*)d_in[4];
    const float* W_gc1   = (const float*)d_in[5];
    const float* W_gc2   = (const float*)d_in[6];
    const float* ln_g    = (const float*)d_in[7];
    const float* ln_b    = (const float*)d_in[8];
    const float* W_obs   = (const float*)d_in[9];
    const float* b_obs   = (const float*)d_in[10];
    const float* W_gate  = (const float*)d_in[11];
    const float* b_gate  = (const float*)d_in[12];
    const float* W_dec   = (const float*)d_in[13];
    const float* b_dec   = (const float*)d_in[14];
    float* out = (float*)d_out;

    dim3 gcn_grid(5, Bc);   // ceil(307/64) x batches = 320 blocks

    // z0 + pred_0
    k_init<<<Rc / 8, 256>>>(x_seq, W_enc, b_enc, W_dec, b_dec, out);

    for (int t = 0; t < Tc - 1; t++) {
        // h1 = tanh((A @ z) @ W_gc1)     (buf0 -> buf1)
        k_gcn<<<gcn_grid, 256>>>(A, W_gc1, 0, 1);
        // h2 = tanh((A @ h1) @ W_gc2)    (buf1 -> buf2)
        k_gcn<<<gcn_grid, 256>>>(A, W_gc2, 1, 2);
        // LN + z-update + gate + pred_{t+1}
        k_update<<<Rc / 32, 256>>>(x_seq, t, obs_mask, ln_g, ln_b,
                                   W_obs, b_obs, W_gate, b_gate,
                                   W_dec, b_dec, out);
    }
}

// round 16
// speedup vs baseline: 1.7168x; 1.1579x over previous
#include <cuda_runtime.h>
#include <math.h>
#include <stdint.h>

// Problem constants
#define Bc 64
#define Nc 307
#define Tc 64
#define Fc 3
#define Hc 64
#define Rc (Bc * Nc)      // 19648 rows (b,n)
#define LN_EPS 1e-5f

// smem strides (floats) chosen for conflict-free mma fragment loads
#define AS 36             // A tile row stride: bank = (4g + tig) -> unique
#define XS 72             // X tile row stride: bank = (8tig + g) -> unique

// Scratch buffers (static device globals: allocation-free, graph-safe)
__device__ float g_buf0[Rc * Hc];   // z
__device__ float g_buf1[Rc * Hc];   // h1
__device__ float g_buf2[Rc * Hc];   // h2

__device__ __forceinline__ float* bufsel(int i) {
    return (i == 0) ? g_buf0 : ((i == 1) ? g_buf1 : g_buf2);
}

__device__ __forceinline__ float tf32_round(float v) {
    uint32_t r;
    asm("cvt.rna.tf32.f32 %0, %1;" : "=r"(r) : "f"(v));
    return __uint_as_float(r);
}

__device__ __forceinline__ void mma_tf32(float4& c, const uint32_t a[4],
                                         uint32_t b0, uint32_t b1) {
    asm volatile(
        "mma.sync.aligned.m16n8k8.row.col.f32.tf32.tf32.f32 "
        "{%0,%1,%2,%3}, {%4,%5,%6,%7}, {%8,%9}, {%0,%1,%2,%3};\n"
        : "+f"(c.x), "+f"(c.y), "+f"(c.z), "+f"(c.w)
        : "r"(a[0]), "r"(a[1]), "r"(a[2]), "r"(a[3]), "r"(b0), "r"(b1));
}

// ---------------------------------------------------------------------------
// k_init: z0 = x_seq[:,:,0,:] @ W_enc + b_enc ; pred_0 = z0 @ W_dec + b_dec
// ---------------------------------------------------------------------------
__global__ void __launch_bounds__(256) k_init(
    const float* __restrict__ x,
    const float* __restrict__ W_enc, const float* __restrict__ b_enc,
    const float* __restrict__ W_dec, const float* __restrict__ b_dec,
    float* __restrict__ out)
{
    int tid  = threadIdx.x;
    int warp = tid >> 5, lane = tid & 31;
    int r = blockIdx.x * 8 + warp;          // grid = Rc/8 exactly

    const float* xr = x + (size_t)r * Tc * Fc;   // t = 0
    float x0 = xr[0], x1 = xr[1], x2 = xr[2];

    float psum = 0.0f;
#pragma unroll
    for (int j = 0; j < 2; j++) {
        int c = lane + 32 * j;
        float z0 = x0 * W_enc[0 * Hc + c] + x1 * W_enc[1 * Hc + c]
                 + x2 * W_enc[2 * Hc + c] + b_enc[c];
        g_buf0[(size_t)r * Hc + c] = z0;
        psum += z0 * W_dec[c];
    }
#pragma unroll
    for (int o = 16; o; o >>= 1) psum += __shfl_xor_sync(0xffffffffu, psum, o);
    if (lane == 0) out[(size_t)r * Tc + 0] = psum + b_dec[0];
}

// ---------------------------------------------------------------------------
// k_gcn: fused GCN layer with tf32 tensor-core mainloop (3xTF32 compensated).
//   S[64x64 tile] = A[n0:n0+64, :] @ Z_b     (K=307 in 32-chunks, mma tf32)
//   H = tanh(S @ W)                          (fp32 epilogue, W via __ldg)
// 256 threads = 8 warps: warp_m = w&3 (16 M-rows), warp_n = w>>2 (32 N-cols).
// Grid: (5, 64) = 320 blocks. smem 36.9 KB (Ss aliases the tile region).
// ---------------------------------------------------------------------------
__global__ void __launch_bounds__(256) k_gcn(
    const float* __restrict__ Amat, const float* __restrict__ W,
    int src, int dst)
{
    __shared__ __align__(16) float sm[2 * 64 * AS + 2 * 32 * XS];  // 9216 floats
    float* A_hi = sm;                       // 64*36
    float* A_lo = sm + 64 * AS;             // 64*36
    float* X_hi = sm + 2 * 64 * AS;         // 32*72
    float* X_lo = sm + 2 * 64 * AS + 32 * XS;
    float (*Ss)[68] = (float(*)[68])sm;     // 64*68 floats, aliases tiles

    const float* X = bufsel(src);
    float* C = bufsel(dst);

    int b  = blockIdx.y;
    int n0 = blockIdx.x * 64;
    int tid = threadIdx.x;
    int w = tid >> 5, lane = tid & 31;
    int g = lane >> 2, tig = lane & 3;
    int wm = (w & 3) * 16;       // warp M offset
    int wn = (w >> 2) * 32;      // warp N offset

    const float* Xb = X + (size_t)b * (Nc * Hc);
    float* Cb = C + (size_t)b * (Nc * Hc);

    float4 Cacc[4];
#pragma unroll
    for (int i = 0; i < 4; i++) Cacc[i] = make_float4(0.f, 0.f, 0.f, 0.f);

    for (int k0 = 0; k0 < Nc; k0 += 32) {
        __syncthreads();
        // A tile (64 rows x 32 k): hi/lo split, layout [row][AS]
        {
            int kk = tid & 31, rr = tid >> 5;   // rr 0..7
            int k = k0 + kk;
#pragma unroll
            for (int i = 0; i < 8; i++) {
                int row = rr + i * 8;
                int n = n0 + row;
                float v = (n < Nc && k < Nc) ? Amat[(size_t)n * Nc + k] : 0.0f;
                float hi = tf32_round(v);
                A_hi[row * AS + kk] = hi;
                A_lo[row * AS + kk] = tf32_round(v - hi);
            }
        }
        // X tile (32 k-rows x 64 cols): hi/lo split, layout [k][XS]
        {
            int rr = tid >> 4;            // 0..15
            int c4 = (tid & 15) * 4;
#pragma unroll
            for (int i = 0; i < 2; i++) {
                int krow = rr + i * 16;
                int k = k0 + krow;
                float4 v;
                if (k < Nc) v = *(const float4*)(&Xb[(size_t)k * Hc + c4]);
                else        v = make_float4(0.f, 0.f, 0.f, 0.f);
                float4 hv, lv;
                hv.x = tf32_round(v.x); lv.x = tf32_round(v.x - hv.x);
                hv.y = tf32_round(v.y); lv.y = tf32_round(v.y - hv.y);
                hv.z = tf32_round(v.z); lv.z = tf32_round(v.z - hv.z);
                hv.w = tf32_round(v.w); lv.w = tf32_round(v.w - hv.w);
                *(float4*)(&X_hi[krow * XS + c4]) = hv;
                *(float4*)(&X_lo[krow * XS + c4]) = lv;
            }
        }
        __syncthreads();

#pragma unroll
        for (int ks = 0; ks < 4; ks++) {
            int kb = ks * 8;
            uint32_t ah[4], al[4];
            ah[0] = __float_as_uint(A_hi[(wm + g    ) * AS + kb + tig    ]);
            ah[1] = __float_as_uint(A_hi[(wm + g + 8) * AS + kb + tig    ]);
            ah[2] = __float_as_uint(A_hi[(wm + g    ) * AS + kb + tig + 4]);
            ah[3] = __float_as_uint(A_hi[(wm + g + 8) * AS + kb + tig + 4]);
            al[0] = __float_as_uint(A_lo[(wm + g    ) * AS + kb + tig    ]);
            al[1] = __float_as_uint(A_lo[(wm + g + 8) * AS + kb + tig    ]);
            al[2] = __float_as_uint(A_lo[(wm + g    ) * AS + kb + tig + 4]);
            al[3] = __float_as_uint(A_lo[(wm + g + 8) * AS + kb + tig + 4]);
#pragma unroll
            for (int nt = 0; nt < 4; nt++) {
                int nc = wn + nt * 8 + g;
                uint32_t bh0 = __float_as_uint(X_hi[(kb + tig    ) * XS + nc]);
                uint32_t bh1 = __float_as_uint(X_hi[(kb + tig + 4) * XS + nc]);
                uint32_t bl0 = __float_as_uint(X_lo[(kb + tig    ) * XS + nc]);
                uint32_t bl1 = __float_as_uint(X_lo[(kb + tig + 4) * XS + nc]);
                mma_tf32(Cacc[nt], ah, bh0, bh1);   // hi*hi
                mma_tf32(Cacc[nt], ah, bl0, bl1);   // hi*lo
                mma_tf32(Cacc[nt], al, bh0, bh1);   // lo*hi
            }
        }
    }

    // Aliasing hazard: all warps done reading tiles before Ss overwrite
    __syncthreads();

    // Write S tile to smem per mma C-fragment layout
#pragma unroll
    for (int nt = 0; nt < 4; nt++) {
        int col = wn + nt * 8 + tig * 2;
        *(float2*)(&Ss[wm + g    ][col]) = make_float2(Cacc[nt].x, Cacc[nt].y);
        *(float2*)(&Ss[wm + g + 8][col]) = make_float2(Cacc[nt].z, Cacc[nt].w);
    }
    __syncthreads();

    // Epilogue: H = tanh(S @ W), fp32 4x4 microtile, W via __ldg (L1-resident)
    int tx = tid & 15;        // col quad
    int ty = tid >> 4;        // row quad (0..15)
    float o[4][4];
#pragma unroll
    for (int i = 0; i < 4; i++)
#pragma unroll
        for (int j = 0; j < 4; j++) o[i][j] = 0.0f;

#pragma unroll 4
    for (int k = 0; k < Hc; k++) {
        float4 wv = __ldg((const float4*)(&W[k * Hc + tx * 4]));
        float s0 = Ss[ty * 4 + 0][k];
        float s1 = Ss[ty * 4 + 1][k];
        float s2 = Ss[ty * 4 + 2][k];
        float s3 = Ss[ty * 4 + 3][k];
        o[0][0] += s0 * wv.x; o[0][1] += s0 * wv.y; o[0][2] += s0 * wv.z; o[0][3] += s0 * wv.w;
        o[1][0] += s1 * wv.x; o[1][1] += s1 * wv.y; o[1][2] += s1 * wv.z; o[1][3] += s1 * wv.w;
        o[2][0] += s2 * wv.x; o[2][1] += s2 * wv.y; o[2][2] += s2 * wv.z; o[2][3] += s2 * wv.w;
        o[3][0] += s3 * wv.x; o[3][1] += s3 * wv.y; o[3][2] += s3 * wv.z; o[3][3] += s3 * wv.w;
    }

#pragma unroll
    for (int i = 0; i < 4; i++) {
        int n = n0 + ty * 4 + i;
        if (n < Nc) {
            float4 h;
            h.x = tanhf(o[i][0]); h.y = tanhf(o[i][1]);
            h.z = tanhf(o[i][2]); h.w = tanhf(o[i][3]);
            *(float4*)(&Cb[(size_t)n * Hc + tx * 4]) = h;
        }
    }
}

// ---------------------------------------------------------------------------
// k_update: step tail, 32 rows per block, 256 threads (R12 version, measured).
// Phase 1 (warp per 4 rows): LN(h2) -> delta; zn = 2z + delta; zo = x@W_obs+b.
// Phase 2 (thread = 2 rows x 4 cols): gate = sigmoid([zn,zo]@W_gate + b);
//   z' = zn + gate*(zo-zn)*mask; pred_{t+1} = z'@W_dec + b_dec.
// ---------------------------------------------------------------------------
__global__ void __launch_bounds__(256) k_update(
    const float* __restrict__ x, int t,
    const float* __restrict__ mask,
    const float* __restrict__ ln_g, const float* __restrict__ ln_b,
    const float* __restrict__ W_obs, const float* __restrict__ b_obs,
    const float* __restrict__ W_gate, const float* __restrict__ b_gate,
    const float* __restrict__ W_dec, const float* __restrict__ b_dec,
    float* __restrict__ out)
{
    __shared__ __align__(16) float s_wg[2 * Hc * Hc];  // 32 KB, natural [k][c]
    __shared__ __align__(16) float s_zn[32][68];
    __shared__ __align__(16) float s_zo[32][68];
    __shared__ float s_m[32];

    int tid = threadIdx.x;
    // stage W_gate (float4)
    {
        const float4* w4 = (const float4*)W_gate;
        float4* sw4 = (float4*)s_wg;
#pragma unroll
        for (int i = 0; i < (2 * Hc * Hc / 4) / 256; i++)
            sw4[tid + i * 256] = w4[tid + i * 256];
    }

    int warp = tid >> 5, lane = tid & 31;
    int rbase = blockIdx.x * 32;             // grid = Rc/32 exactly (614)

    // Phase 1: each warp handles 4 rows
#pragma unroll
    for (int p = 0; p < 4; p++) {
        int lr = warp * 4 + p;               // local row 0..31
        int r = rbase + lr;

        float h0 = g_buf2[(size_t)r * Hc + lane];
        float h1 = g_buf2[(size_t)r * Hc + lane + 32];

        float s = h0 + h1;
#pragma unroll
        for (int o = 16; o; o >>= 1) s += __shfl_xor_sync(0xffffffffu, s, o);
        float mu = s * (1.0f / Hc);

        float d0 = h0 - mu, d1 = h1 - mu;
        float v = d0 * d0 + d1 * d1;
#pragma unroll
        for (int o = 16; o; o >>= 1) v += __shfl_xor_sync(0xffffffffu, v, o);
        float rstd = rsqrtf(v * (1.0f / Hc) + LN_EPS);

        const float* xr = x + ((size_t)r * Tc + (t + 1)) * Fc;
        float x0 = xr[0], x1 = xr[1], x2 = xr[2];

#pragma unroll
        for (int j = 0; j < 2; j++) {
            int c = lane + 32 * j;
            float hv = j ? h1 : h0;
            float delta = (hv - mu) * rstd * ln_g[c] + ln_b[c];
            float zn = 2.0f * g_buf0[(size_t)r * Hc + c] + delta;
            float zo = x0 * W_obs[0 * Hc + c] + x1 * W_obs[1 * Hc + c]
                     + x2 * W_obs[2 * Hc + c] + b_obs[c];
            s_zn[lr][c] = zn;
            s_zo[lr][c] = zo;
        }
        if (lane == 0) s_m[lr] = mask[r];
    }
    __syncthreads();

    // Phase 2: rg = tid>>4 (0..15) handles rows rg and rg+16; cols (tid&15)*4
    int rg = tid >> 4;
    int c4 = (tid & 15) * 4;

    float4 bg = *(const float4*)(&b_gate[c4]);
    float4 acc0 = bg, acc1 = bg;

#pragma unroll 4
    for (int k = 0; k < Hc; k++) {
        float4 w0 = *(const float4*)(&s_wg[k * Hc + c4]);
        float4 w1 = *(const float4*)(&s_wg[(Hc + k) * Hc + c4]);

        float z0 = s_zn[rg][k],      o0 = s_zo[rg][k];
        float z1 = s_zn[rg + 16][k], o1 = s_zo[rg + 16][k];

        acc0.x += z0 * w0.x + o0 * w1.x; acc0.y += z0 * w0.y + o0 * w1.y;
        acc0.z += z0 * w0.z + o0 * w1.z; acc0.w += z0 * w0.w + o0 * w1.w;
        acc1.x += z1 * w0.x + o1 * w1.x; acc1.y += z1 * w0.y + o1 * w1.y;
        acc1.z += z1 * w0.z + o1 * w1.z; acc1.w += z1 * w0.w + o1 * w1.w;
    }

    float4 wd = *(const float4*)(&W_dec[c4]);

#pragma unroll
    for (int j = 0; j < 2; j++) {
        int lr = rg + 16 * j;
        int r = rbase + lr;
        float m = s_m[lr];
        float4 a = (j == 0) ? acc0 : acc1;
        float4 zn = *(const float4*)(&s_zn[lr][c4]);
        float4 zo = *(const float4*)(&s_zo[lr][c4]);
        float4 zf;
        zf.x = zn.x + (zo.x - zn.x) * m / (1.0f + expf(-a.x));
        zf.y = zn.y + (zo.y - zn.y) * m / (1.0f + expf(-a.y));
        zf.z = zn.z + (zo.z - zn.z) * m / (1.0f + expf(-a.z));
        zf.w = zn.w + (zo.w - zn.w) * m / (1.0f + expf(-a.w));

        *(float4*)(&g_buf0[(size_t)r * Hc + c4]) = zf;

        // pred: reduce zf . W_dec over 16 lanes of this row (half-warp group)
        float psum = zf.x * wd.x + zf.y * wd.y + zf.z * wd.z + zf.w * wd.w;
#pragma unroll
        for (int o = 8; o; o >>= 1) psum += __shfl_xor_sync(0xffffffffu, psum, o);
        if ((tid & 15) == 0) out[(size_t)r * Tc + (t + 1)] = psum + b_dec[0];
    }
}

// ---------------------------------------------------------------------------
// Host launcher (graph-capturable: kernel launches only)
// ---------------------------------------------------------------------------
extern "C" void kernel_launch(void* const* d_in, const int* in_sizes, int n_in,
                              void* d_out, int out_size)
{
    (void)in_sizes; (void)n_in; (void)out_size;
    const float* x_seq   = (const float*)d_in[0];
    const float* obs_mask= (const float*)d_in[1];
    const float* A       = (const float*)d_in[2];
    const float* W_enc   = (const float*)d_in[3];
    const float* b_enc   = (const float*)d_in[4];
    const float* W_gc1   = (const float*)d_in[5];
    const float* W_gc2   = (const float*)d_in[6];
    const float* ln_g    = (const float*)d_in[7];
    const float* ln_b    = (const float*)d_in[8];
    const float* W_obs   = (const float*)d_in[9];
    const float* b_obs   = (const float*)d_in[10];
    const float* W_gate  = (const float*)d_in[11];
    const float* b_gate  = (const float*)d_in[12];
    const float* W_dec   = (const float*)d_in[13];
    const float* b_dec   = (const float*)d_in[14];
    float* out = (float*)d_out;

    dim3 gcn_grid(5, Bc);   // ceil(307/64) x batches = 320 blocks

    // z0 + pred_0
    k_init<<<Rc / 8, 256>>>(x_seq, W_enc, b_enc, W_dec, b_dec, out);

    for (int t = 0; t < Tc - 1; t++) {
        // h1 = tanh((A @ z) @ W_gc1)     (buf0 -> buf1)
        k_gcn<<<gcn_grid, 256>>>(A, W_gc1, 0, 1);
        // h2 = tanh((A @ h1) @ W_gc2)    (buf1 -> buf2)
        k_gcn<<<gcn_grid, 256>>>(A, W_gc2, 1, 2);
        // LN + z-update + gate + pred_{t+1}
        k_update<<<Rc / 32, 256>>>(x_seq, t, obs_mask, ln_g, ln_b,
                                   W_obs, b_obs, W_gate, b_gate,
                                   W_dec, b_dec, out);
    }
}